// round 2
// baseline (speedup 1.0000x reference)
#include <cuda_runtime.h>
#include <math.h>

#define DIM 256
#define NGATES 46   // fused Rz*Ry*Rx rotations: 16 + 14 + 16

// Scratch: W[d][c], d = input basis index (K dim), c in [0,512): Re U[k][d] (c=k), Im U[k][d] (c=256+k)
__device__ float g_W[DIM * 512];

struct Cplx { float x, y; };
__device__ __forceinline__ Cplx cmul(Cplx a, Cplx b) { return {a.x*b.x - a.y*b.y, a.x*b.y + a.y*b.x}; }
__device__ __forceinline__ Cplx cadd(Cplx a, Cplx b) { return {a.x + b.x, a.y + b.y}; }

// One block per basis state column. 128 threads, state (256 complex) in shared.
__global__ void build_U_kernel(const float* __restrict__ th1,
                               const float* __restrict__ th2,
                               const float* __restrict__ th3) {
    __shared__ float2 s[DIM];
    __shared__ Cplx M[NGATES][4];   // fused rotation matrices [00,01,10,11]

    const int tid = threadIdx.x;       // 0..127
    const int col = blockIdx.x;        // basis state

    // Precompute all fused gate matrices (one thread per gate)
    if (tid < NGATES) {
        int g = tid, a, r;
        if (g < 16)      { a = 0; r = g; }
        else if (g < 30) { a = 1; r = g - 16; }
        else             { a = 2; r = g - 30; }
        const float* th = (a == 0) ? th1 : ((a == 1) ? th2 : th3);
        float t1 = th[r*3 + 0], t2 = th[r*3 + 1], t3 = th[r*3 + 2];
        float cx, sx, cy, sy, cz, sz;
        sincosf(0.5f * t1, &sx, &cx);
        sincosf(0.5f * t2, &sy, &cy);
        sincosf(0.5f * t3, &sz, &cz);
        // A = Ry * Rx
        Cplx A00 = { cy*cx,  sy*sx};
        Cplx A01 = {-sy*cx, -cy*sx};
        Cplx A10 = { sy*cx, -cy*sx};
        Cplx A11 = { cy*cx, -sy*sx};
        Cplx em = {cz, -sz}, ep = {cz, sz};   // Rz diag
        M[g][0] = cmul(em, A00);
        M[g][1] = cmul(em, A01);
        M[g][2] = cmul(ep, A10);
        M[g][3] = cmul(ep, A11);
    }

    // init |col>
    for (int k = tid; k < DIM; k += 128)
        s[k] = make_float2(k == col ? 1.0f : 0.0f, 0.0f);
    __syncthreads();

    const int nqs[3] = {8, 7, 8};
    int g = 0;
    for (int a = 0; a < 3; a++) {
        const int nq = nqs[a];
        for (int d = 0; d < 2; d++) {
            // rotations on qubits 0..nq-1
            for (int q = 0; q < nq; q++) {
                Cplx m00 = M[g][0], m01 = M[g][1], m10 = M[g][2], m11 = M[g][3];
                g++;
                int p = tid;
                int i0 = ((p >> q) << (q + 1)) | (p & ((1 << q) - 1));
                int i1 = i0 | (1 << q);
                float2 a0 = s[i0], a1 = s[i1];
                Cplx ca0 = {a0.x, a0.y}, ca1 = {a1.x, a1.y};
                Cplx n0 = cadd(cmul(m00, ca0), cmul(m01, ca1));
                Cplx n1 = cadd(cmul(m10, ca0), cmul(m11, ca1));
                s[i0] = make_float2(n0.x, n0.y);
                s[i1] = make_float2(n1.x, n1.y);
                __syncthreads();
            }
            // CX chain: control q, target q+1 (adjacent bits)
            for (int q = 0; q < nq - 1; q++) {
                if (tid < 64) {
                    int m = tid;  // 6 free bits
                    int base = ((m >> q) << (q + 2)) | (m & ((1 << q) - 1));
                    int i0 = base | (1 << q);            // control=1, target=0
                    int i1 = i0 | (2 << q);              // control=1, target=1
                    float2 t = s[i0]; s[i0] = s[i1]; s[i1] = t;
                }
                __syncthreads();
            }
        }
    }

    // write out: W[col][k] = Re s[k], W[col][256+k] = Im s[k]
    for (int k = tid; k < DIM; k += 128) {
        g_W[col * 512 + k]       = s[k].x;
        g_W[col * 512 + 256 + k] = s[k].y;
    }
}

// Fused GEMM + epilogue.
// Block: 32 rows x 512 cols (full N, full K reduction). 256 threads:
//   ty = tid/32 (warp, 4 rows), tx = tid%32 (16 cols each).
__global__ __launch_bounds__(256, 2)
void pqc_gemm_kernel(const float* __restrict__ x, float* __restrict__ out) {
    __shared__ float Xs[16][36];     // [k][row], padded
    __shared__ float Ws[16][512];    // [k][col]

    const int tid = threadIdx.x;
    const int tx = tid & 31;
    const int ty = tid >> 5;
    const int row0 = blockIdx.x * 32;

    float acc[4][16];
#pragma unroll
    for (int i = 0; i < 4; i++)
#pragma unroll
        for (int j = 0; j < 16; j++) acc[i][j] = 0.0f;

    for (int kb = 0; kb < 256; kb += 16) {
        __syncthreads();
        // X tile: 32 rows x 16 k (transpose into Xs[k][row])
        if (tid < 128) {
            int m = tid >> 2, k4 = tid & 3;
            float4 v = *(const float4*)(x + (size_t)(row0 + m) * 256 + kb + k4 * 4);
            Xs[k4*4 + 0][m] = v.x;
            Xs[k4*4 + 1][m] = v.y;
            Xs[k4*4 + 2][m] = v.z;
            Xs[k4*4 + 3][m] = v.w;
        }
        // W tile: 16 k x 512 cols (L2-resident source)
#pragma unroll
        for (int r = 0; r < 8; r++) {
            int slot = tid + r * 256;          // 0..2047 float4 slots
            int kr = slot >> 7, c4 = slot & 127;
            *(float4*)&Ws[kr][c4 * 4] = *(const float4*)&g_W[(kb + kr) * 512 + c4 * 4];
        }
        __syncthreads();

#pragma unroll
        for (int k = 0; k < 16; k++) {
            float4 xv = *(const float4*)&Xs[k][ty * 4];
            float xr[4] = {xv.x, xv.y, xv.z, xv.w};
            float w[16];
            *(float4*)&w[0]  = *(const float4*)&Ws[k][tx * 16 + 0];
            *(float4*)&w[4]  = *(const float4*)&Ws[k][tx * 16 + 4];
            *(float4*)&w[8]  = *(const float4*)&Ws[k][tx * 16 + 8];
            *(float4*)&w[12] = *(const float4*)&Ws[k][tx * 16 + 12];
#pragma unroll
            for (int i = 0; i < 4; i++)
#pragma unroll
                for (int j = 0; j < 16; j++)
                    acc[i][j] = fmaf(xr[i], w[j], acc[i][j]);
        }
    }

    // Epilogue: y_j = sum_c S[j][c&255] * acc_c^2  (zr and zi halves contribute additively)
    float y[4][8];
#pragma unroll
    for (int i = 0; i < 4; i++)
#pragma unroll
        for (int ob = 0; ob < 8; ob++) y[i][ob] = 0.0f;

#pragma unroll
    for (int j = 0; j < 16; j++) {
        int kk = (tx * 16 + j) & 255;
#pragma unroll
        for (int i = 0; i < 4; i++) {
            float p = acc[i][j] * acc[i][j];
#pragma unroll
            for (int ob = 0; ob < 8; ob++) {
                y[i][ob] += ((kk >> (7 - ob)) & 1) ? -p : p;
            }
        }
    }

    // Warp butterfly reduce across tx (all 32 lanes of a warp share the same 4 rows)
#pragma unroll
    for (int off = 16; off; off >>= 1)
#pragma unroll
        for (int i = 0; i < 4; i++)
#pragma unroll
            for (int ob = 0; ob < 8; ob++)
                y[i][ob] += __shfl_xor_sync(0xffffffffu, y[i][ob], off);

    // out[row][c] = (y_c)^2 / sum(y^2) for c<8, else 0
#pragma unroll
    for (int i = 0; i < 4; i++) {
        float n2 = 0.0f;
#pragma unroll
        for (int ob = 0; ob < 8; ob++) n2 += y[i][ob] * y[i][ob];
        float inv = 1.0f / fmaxf(n2, 1e-30f);
        float* orow = out + (size_t)(row0 + ty * 4 + i) * 256;
#pragma unroll
        for (int cc = 0; cc < 8; cc++) {
            int c = tx + cc * 32;
            float v = 0.0f;
            if (c < 8) { float t = y[i][c]; v = t * t * inv; }
            orow[c] = v;
        }
    }
}

extern "C" void kernel_launch(void* const* d_in, const int* in_sizes, int n_in,
                              void* d_out, int out_size) {
    const float* x   = (const float*)d_in[0];
    const float* th1 = (const float*)d_in[1];
    const float* th2 = (const float*)d_in[2];
    const float* th3 = (const float*)d_in[3];
    float* out = (float*)d_out;

    int nrows = in_sizes[0] / 256;   // 32768

    build_U_kernel<<<256, 128>>>(th1, th2, th3);
    pqc_gemm_kernel<<<nrows / 32, 256>>>(x, out);
}

// round 4
// speedup vs baseline: 4.1798x; 4.1798x over previous
#include <cuda_runtime.h>
#include <cuda_bf16.h>
#include <stdint.h>
#include <math.h>

#define DIM 256
#define NGATES 46
#define NROWS 32768
#define BM 128
#define BN 256
#define KC 64
#define KTOT 768
#define NCH (KTOT / KC)      // 12
#define THREADS 512
#define STAGES 3
#define APITCH 72            // 64 + 8 pad (bf16 elems)
#define AS_ELE (BM * APITCH)     // 9216
#define BS_ELE (BN * APITCH)     // 18432
#define AS_BYTES (AS_ELE * 2)
#define BS_BYTES (BS_ELE * 2)
#define SMEM_YPART_OFF (STAGES * (AS_BYTES + BS_BYTES))           // 165888
#define SMEM_YS_OFF (SMEM_YPART_OFF + 4 * BM * 8 * 4)             // +16384
#define SMEM_TOTAL (SMEM_YS_OFF + BM * 8 * 4)                     // +4096 = 186368

// Scratch (device globals — no allocation)
__device__ __nv_bfloat16 g_Xcat[(size_t)NROWS * 512];   // [row][hi(256) | lo(256)]
__device__ __nv_bfloat16 g_Wcat[512 * KTOT];            // [c][hi(256) | lo(256) | hi(256)]

struct Cplx { float x, y; };
__device__ __forceinline__ Cplx cmul(Cplx a, Cplx b) { return {a.x*b.x - a.y*b.y, a.x*b.y + a.y*b.x}; }
__device__ __forceinline__ Cplx cadd(Cplx a, Cplx b) { return {a.x + b.x, a.y + b.y}; }

// ---------------- build U columns, write split-bf16 Wcat ----------------
__global__ void build_U_kernel(const float* __restrict__ th1,
                               const float* __restrict__ th2,
                               const float* __restrict__ th3) {
    __shared__ float2 s[DIM];
    __shared__ Cplx M[NGATES][4];

    const int tid = threadIdx.x;       // 0..127
    const int col = blockIdx.x;        // basis state d

    if (tid < NGATES) {
        int g = tid, a, r;
        if (g < 16)      { a = 0; r = g; }
        else if (g < 30) { a = 1; r = g - 16; }
        else             { a = 2; r = g - 30; }
        const float* th = (a == 0) ? th1 : ((a == 1) ? th2 : th3);
        float t1 = th[r*3 + 0], t2 = th[r*3 + 1], t3 = th[r*3 + 2];
        float cx, sx, cy, sy, cz, sz;
        sincosf(0.5f * t1, &sx, &cx);
        sincosf(0.5f * t2, &sy, &cy);
        sincosf(0.5f * t3, &sz, &cz);
        Cplx A00 = { cy*cx,  sy*sx};
        Cplx A01 = {-sy*cx, -cy*sx};
        Cplx A10 = { sy*cx, -cy*sx};
        Cplx A11 = { cy*cx, -sy*sx};
        Cplx em = {cz, -sz}, ep = {cz, sz};
        M[g][0] = cmul(em, A00);
        M[g][1] = cmul(em, A01);
        M[g][2] = cmul(ep, A10);
        M[g][3] = cmul(ep, A11);
    }

    for (int k = tid; k < DIM; k += 128)
        s[k] = make_float2(k == col ? 1.0f : 0.0f, 0.0f);
    __syncthreads();

    const int nqs[3] = {8, 7, 8};
    int g = 0;
    for (int a = 0; a < 3; a++) {
        const int nq = nqs[a];
        for (int d = 0; d < 2; d++) {
            for (int q = 0; q < nq; q++) {
                Cplx m00 = M[g][0], m01 = M[g][1], m10 = M[g][2], m11 = M[g][3];
                g++;
                int p = tid;
                int i0 = ((p >> q) << (q + 1)) | (p & ((1 << q) - 1));
                int i1 = i0 | (1 << q);
                float2 a0 = s[i0], a1 = s[i1];
                Cplx ca0 = {a0.x, a0.y}, ca1 = {a1.x, a1.y};
                Cplx n0 = cadd(cmul(m00, ca0), cmul(m01, ca1));
                Cplx n1 = cadd(cmul(m10, ca0), cmul(m11, ca1));
                s[i0] = make_float2(n0.x, n0.y);
                s[i1] = make_float2(n1.x, n1.y);
                __syncthreads();
            }
            for (int q = 0; q < nq - 1; q++) {
                if (tid < 64) {
                    int m = tid;
                    int base = ((m >> q) << (q + 2)) | (m & ((1 << q) - 1));
                    int i0 = base | (1 << q);
                    int i1 = i0 | (2 << q);
                    float2 t = s[i0]; s[i0] = s[i1]; s[i1] = t;
                }
                __syncthreads();
            }
        }
    }

    // Wcat[c][d'] with K' segments [hi | lo | hi]; c = k (Re), 256+k (Im)
    for (int k = tid; k < DIM; k += 128) {
        float re = s[k].x, im = s[k].y;
        __nv_bfloat16 rh = __float2bfloat16(re);
        __nv_bfloat16 rl = __float2bfloat16(re - __bfloat162float(rh));
        __nv_bfloat16 ih = __float2bfloat16(im);
        __nv_bfloat16 il = __float2bfloat16(im - __bfloat162float(ih));
        g_Wcat[(size_t)k * KTOT + col]         = rh;
        g_Wcat[(size_t)k * KTOT + 256 + col]   = rl;
        g_Wcat[(size_t)k * KTOT + 512 + col]   = rh;
        g_Wcat[(size_t)(256 + k) * KTOT + col]       = ih;
        g_Wcat[(size_t)(256 + k) * KTOT + 256 + col] = il;
        g_Wcat[(size_t)(256 + k) * KTOT + 512 + col] = ih;
    }
}

// ---------------- split X into bf16 hi/lo ----------------
__global__ void prep_x_kernel(const float* __restrict__ x) {
    int idx = blockIdx.x * blockDim.x + threadIdx.x;   // one float4
    int row = idx >> 6;
    int q = idx & 63;
    float4 v = reinterpret_cast<const float4*>(x)[idx];
    float f[4] = {v.x, v.y, v.z, v.w};
    __nv_bfloat16 h[4], l[4];
#pragma unroll
    for (int i = 0; i < 4; i++) {
        h[i] = __float2bfloat16(f[i]);
        l[i] = __float2bfloat16(f[i] - __bfloat162float(h[i]));
    }
    __nv_bfloat162* ph = reinterpret_cast<__nv_bfloat162*>(&g_Xcat[(size_t)row * 512 + q * 4]);
    ph[0] = __nv_bfloat162{h[0], h[1]};
    ph[1] = __nv_bfloat162{h[2], h[3]};
    __nv_bfloat162* pl = reinterpret_cast<__nv_bfloat162*>(&g_Xcat[(size_t)row * 512 + 256 + q * 4]);
    pl[0] = __nv_bfloat162{l[0], l[1]};
    pl[1] = __nv_bfloat162{l[2], l[3]};
}

// ---------------- GEMM + epilogue ----------------
__device__ __forceinline__ void cpa16(unsigned int d, const void* s) {
    asm volatile("cp.async.cg.shared.global [%0], [%1], 16;\n" :: "r"(d), "l"(s));
}
#define CP_COMMIT() asm volatile("cp.async.commit_group;\n" ::: "memory")
#define CP_WAIT(N)  asm volatile("cp.async.wait_group %0;\n" :: "n"(N) : "memory")

#define LDSM4(R0,R1,R2,R3,ADDR) \
    asm volatile("ldmatrix.sync.aligned.m8n8.x4.shared.b16 {%0,%1,%2,%3}, [%4];" \
        : "=r"(R0), "=r"(R1), "=r"(R2), "=r"(R3) : "r"(ADDR))

#define MMA16816(C, A, B0, B1) \
    asm volatile("mma.sync.aligned.m16n8k16.row.col.f32.bf16.bf16.f32 " \
        "{%0,%1,%2,%3},{%4,%5,%6,%7},{%8,%9},{%0,%1,%2,%3};" \
        : "+f"((C)[0]), "+f"((C)[1]), "+f"((C)[2]), "+f"((C)[3]) \
        : "r"((A)[0]), "r"((A)[1]), "r"((A)[2]), "r"((A)[3]), "r"(B0), "r"(B1))

__device__ __forceinline__ void load_chunk(char* smem, int tid, int buf, int ci,
                                           int row0, int n0) {
    int kc = ci * KC;
    int srcA = (kc < 512) ? (kc & 255) : (kc - 256);
    unsigned int sA = (unsigned int)__cvta_generic_to_shared(smem) + buf * AS_BYTES;
    unsigned int sB = (unsigned int)__cvta_generic_to_shared(smem) + STAGES * AS_BYTES + buf * BS_BYTES;
#pragma unroll
    for (int p = 0; p < 2; p++) {
        int u = tid + p * THREADS;
        int r = u >> 3, ch = u & 7;
        cpa16(sA + (r * APITCH + ch * 8) * 2,
              &g_Xcat[(size_t)(row0 + r) * 512 + srcA + ch * 8]);
    }
#pragma unroll
    for (int p = 0; p < 4; p++) {
        int u = tid + p * THREADS;
        int r = u >> 3, ch = u & 7;
        cpa16(sB + (r * APITCH + ch * 8) * 2,
              &g_Wcat[(size_t)(n0 + r) * KTOT + kc + ch * 8]);
    }
    CP_COMMIT();
}

__global__ __launch_bounds__(THREADS, 1)
void pqc_mma_kernel(float* __restrict__ out) {
    extern __shared__ char smem[];
    float* ypart = reinterpret_cast<float*>(smem + SMEM_YPART_OFF);  // [4][128][8]
    float* ys    = reinterpret_cast<float*>(smem + SMEM_YS_OFF);     // [128][8]

    const int tid = threadIdx.x;
    const int l = tid & 31;
    const int wid = tid >> 5;
    const int wm = wid & 3;        // row group (32 rows)
    const int wn = wid >> 2;       // col group (64 cols)
    const int row0 = blockIdx.x * BM;

    const unsigned int smem_u32 = (unsigned int)__cvta_generic_to_shared(smem);

    for (int nc = 0; nc < 2; nc++) {
        const int n0 = nc * BN;
        float acc[2][8][4];
#pragma unroll
        for (int mt = 0; mt < 2; mt++)
#pragma unroll
            for (int nt = 0; nt < 8; nt++)
#pragma unroll
                for (int e = 0; e < 4; e++) acc[mt][nt][e] = 0.0f;

        load_chunk(smem, tid, 0, 0, row0, n0);
        load_chunk(smem, tid, 1, 1, row0, n0);

        for (int ci = 0; ci < NCH; ci++) {
            int buf = ci % STAGES;
            if (ci + STAGES - 1 < NCH)
                load_chunk(smem, tid, (ci + STAGES - 1) % STAGES, ci + STAGES - 1, row0, n0);
            if (ci < NCH - 2)      { CP_WAIT(2); }
            else if (ci == NCH - 2){ CP_WAIT(1); }
            else                   { CP_WAIT(0); }
            __syncthreads();

            unsigned int aBase = smem_u32 + buf * AS_BYTES;
            unsigned int bBase = smem_u32 + STAGES * AS_BYTES + buf * BS_BYTES;
#pragma unroll
            for (int kk = 0; kk < KC; kk += 16) {
                unsigned int a[2][4], b[4][4];
#pragma unroll
                for (int mt = 0; mt < 2; mt++) {
                    int r = wm * 32 + mt * 16 + (l & 15);
                    unsigned int addr = aBase + (r * APITCH + kk + 8 * (l >> 4)) * 2;
                    LDSM4(a[mt][0], a[mt][1], a[mt][2], a[mt][3], addr);
                }
#pragma unroll
                for (int bn = 0; bn < 4; bn++) {
                    int n = wn * 64 + bn * 16 + (l & 7) + ((l >> 4) & 1) * 8;
                    int k = kk + ((l >> 3) & 1) * 8;
                    unsigned int addr = bBase + (n * APITCH + k) * 2;
                    LDSM4(b[bn][0], b[bn][1], b[bn][2], b[bn][3], addr);
                }
#pragma unroll
                for (int mt = 0; mt < 2; mt++)
#pragma unroll
                    for (int nt = 0; nt < 8; nt++)
                        MMA16816(acc[mt][nt], a[mt],
                                 b[nt >> 1][(nt & 1) * 2], b[nt >> 1][(nt & 1) * 2 + 1]);
            }
            __syncthreads();
        }

        // epilogue: sign-weighted reduction of |z|^2 into y[8] per row.
        // col c = n0 + wn*64 + nt*8 + 2*(l&3) + e; k = c & 255.
        // bits: b0=e(j7), b1=l&1(j6), b2=(l>>1)&1(j5), b3..5=nt(j4,j3,j2), b6=wn&1(j1), b7=wn>>1(j0)
        float yp[2][2][8];
#pragma unroll
        for (int mt = 0; mt < 2; mt++) {
#pragma unroll
            for (int half = 0; half < 2; half++) {
                float s0 = 0.f, T7 = 0.f, T4 = 0.f, T3 = 0.f, T2 = 0.f;
#pragma unroll
                for (int nt = 0; nt < 8; nt++) {
                    float v0 = acc[mt][nt][2 * half];
                    float v1 = acc[mt][nt][2 * half + 1];
                    float p1 = v1 * v1;
                    float ps = v0 * v0 + p1;
                    s0 += ps; T7 += p1;
                    if (nt & 1) T4 += ps;
                    if (nt & 2) T3 += ps;
                    if (nt & 4) T2 += ps;
                }
                yp[mt][half][7] = s0 - 2.f * T7;
                yp[mt][half][4] = s0 - 2.f * T4;
                yp[mt][half][3] = s0 - 2.f * T3;
                yp[mt][half][2] = s0 - 2.f * T2;
                yp[mt][half][6] = (l & 1) ? -s0 : s0;
                yp[mt][half][5] = (l & 2) ? -s0 : s0;
                yp[mt][half][1] = (wn & 1) ? -s0 : s0;
                yp[mt][half][0] = (wn & 2) ? -s0 : s0;
            }
        }
#pragma unroll
        for (int off = 1; off <= 2; off <<= 1)
#pragma unroll
            for (int mt = 0; mt < 2; mt++)
#pragma unroll
                for (int half = 0; half < 2; half++)
#pragma unroll
                    for (int ob = 0; ob < 8; ob++)
                        yp[mt][half][ob] += __shfl_xor_sync(0xffffffffu, yp[mt][half][ob], off);

        if ((l & 3) == 0) {
#pragma unroll
            for (int mt = 0; mt < 2; mt++)
#pragma unroll
                for (int half = 0; half < 2; half++) {
                    int r = wm * 32 + mt * 16 + half * 8 + (l >> 2);
                    float* dst = &ypart[((size_t)wn * BM + r) * 8];
                    if (nc == 0) {
#pragma unroll
                        for (int ob = 0; ob < 8; ob++) dst[ob] = yp[mt][half][ob];
                    } else {
#pragma unroll
                        for (int ob = 0; ob < 8; ob++) dst[ob] += yp[mt][half][ob];
                    }
                }
        }
        __syncthreads();
    }

    // reduce over wn partials
    for (int idx = tid; idx < BM * 8; idx += THREADS) {
        float v = ypart[idx] + ypart[BM * 8 + idx] + ypart[2 * BM * 8 + idx] + ypart[3 * BM * 8 + idx];
        ys[idx] = v;
    }
    __syncthreads();

    // output: out[row][c] = y_c^2 / sum(y^2) for c<8 else 0
    {
        int r = tid >> 2, q = tid & 3;
        float yv[8];
#pragma unroll
        for (int ob = 0; ob < 8; ob++) yv[ob] = ys[r * 8 + ob];
        float n2 = 0.f;
#pragma unroll
        for (int ob = 0; ob < 8; ob++) n2 += yv[ob] * yv[ob];
        float inv = 1.0f / fmaxf(n2, 1e-30f);
        float4* orow = reinterpret_cast<float4*>(out + (size_t)(row0 + r) * 256 + q * 64);
        float4 z4 = make_float4(0.f, 0.f, 0.f, 0.f);
#pragma unroll
        for (int j = 0; j < 16; j++) {
            float4 v = z4;
            if (q == 0 && j == 0)
                v = make_float4(yv[0]*yv[0]*inv, yv[1]*yv[1]*inv, yv[2]*yv[2]*inv, yv[3]*yv[3]*inv);
            else if (q == 0 && j == 1)
                v = make_float4(yv[4]*yv[4]*inv, yv[5]*yv[5]*inv, yv[6]*yv[6]*inv, yv[7]*yv[7]*inv);
            orow[j] = v;
        }
    }
}

extern "C" void kernel_launch(void* const* d_in, const int* in_sizes, int n_in,
                              void* d_out, int out_size) {
    const float* x   = (const float*)d_in[0];
    const float* th1 = (const float*)d_in[1];
    const float* th2 = (const float*)d_in[2];
    const float* th3 = (const float*)d_in[3];
    float* out = (float*)d_out;

    int nrows = in_sizes[0] / 256;   // 32768

    cudaFuncSetAttribute(pqc_mma_kernel,
                         cudaFuncAttributeMaxDynamicSharedMemorySize, SMEM_TOTAL);

    build_U_kernel<<<256, 128>>>(th1, th2, th3);
    prep_x_kernel<<<(nrows * 64) / 256, 256>>>(x);
    pqc_mma_kernel<<<nrows / BM, THREADS, SMEM_TOTAL>>>(out);
}